// round 14
// baseline (speedup 1.0000x reference)
#include <cuda_runtime.h>
#include <cstdint>

// Sparse transposed conv: gather-GEMM-scatter over rulebook.
// x:[N_SRC,32] f32, weight:[K,32,16] f32, src/dst:[K,M] i32, out:[N_TGT,16] f32.
// v13 = v12 (TMA bulk gather, 144B skewed rows, 4-lane-per-pair, f32x2 FMA,
//       red.v4 scatter) with ALU fat removed:
//       - only warp 0 waits on the mbarrier; rest sleep in __syncthreads
//       - dst prefetch hoisted; row addressing strength-reduced

#define CIN   32
#define COUT  16
#define TPB   256
#define PPB   256
#define ROWB  144                 // 128B row + 16B pad: bank16 = (r + j) mod 8

typedef unsigned long long ull;
typedef unsigned int       u32;

#define FMA2(acc, a, b) \
    asm("fma.rn.f32x2 %0, %1, %2, %0;" : "+l"(acc) : "l"(a), "l"(b))

#define UNPACK2(lo, hi, v) \
    asm("mov.b64 {%0, %1}, %2;" : "=f"(lo), "=f"(hi) : "l"(v))

// dynamic smem: [0,2048) wsm ; [2048,2056) mbar ; [2176, 2176+256*144) xsm
#define MBAR_OFF 2048
#define XSM_OFF  2176
#define SMEM_BYTES (XSM_OFF + PPB * ROWB)     // 39040

__global__ __launch_bounds__(TPB, 4)
void rulebook_gemm_scatter(const float* __restrict__ x,
                           const float* __restrict__ w,
                           const int*   __restrict__ src_idx,
                           const int*   __restrict__ dst_idx,
                           float*       __restrict__ out,
                           int M)
{
    extern __shared__ char smem[];
    float* wsm = (float*)smem;

    const int k  = blockIdx.y;
    const int pb = blockIdx.x * PPB;
    const int npair = min(PPB, M - pb);
    const long long kb = (long long)k * M + pb;

    u32 smem_b;
    asm("{ .reg .u64 t; cvta.to.shared.u64 t, %1; cvt.u32.u64 %0, t; }"
        : "=r"(smem_b) : "l"(smem));
    const u32 mbar  = smem_b + MBAR_OFF;
    const u32 xsm_b = smem_b + XSM_OFF;

    const int tid = threadIdx.x;

    // ---- mbarrier init + arm (full tile bytes) ----
    if (tid == 0) {
        asm volatile("mbarrier.init.shared.b64 [%0], 1;" :: "r"(mbar) : "memory");
    }
    __syncthreads();
    if (tid == 0) {
        asm volatile("mbarrier.arrive.expect_tx.shared.b64 _, [%0], %1;"
                     :: "r"(mbar), "r"((u32)(PPB * 128)) : "memory");
    }

    // ---- gather: one 128B bulk copy per row (TMA path, off the LSU) ----
    {
        int rc = (tid < npair) ? tid : 0;
        int s = __ldg(src_idx + kb + rc);
        const float* src = x + (size_t)s * CIN;
        u32 dst = xsm_b + (u32)tid * ROWB;
        asm volatile(
            "cp.async.bulk.shared::cta.global.mbarrier::complete_tx::bytes "
            "[%0], [%1], 128, [%2];"
            :: "r"(dst), "l"(src), "r"(mbar) : "memory");
    }

    // stride-64 ownership: group g owns pairs g, g+64, g+128, g+192;
    // lane l owns couts 4l..4l+3.
    const int g = tid >> 2;
    const int l = tid & 3;

    // dst prefetch first (longest latency distance to use)
    int dsts[4];
    #pragma unroll
    for (int ii = 0; ii < 4; ii++) {
        int r = g + 64 * ii;
        dsts[ii] = (r < npair) ? __ldg(dst_idx + kb + r) : -1;
    }

    // ---- weight[k] -> smem, interleaved: word = cp*32 + j*2 + (c&1) ----
    const float* wk = w + (size_t)k * (CIN * COUT);
    #pragma unroll
    for (int i = 0; i < (CIN * COUT) / TPB; i++) {
        int t = i * TPB + tid;
        int c = t >> 4, j = t & 15;
        wsm[(c >> 1) * 32 + j * 2 + (c & 1)] = __ldg(wk + t);
    }

    // ---- wait: warp 0 only (HW-sleep try_wait); others sleep in bar.sync ----
    if (tid < 32) {
        asm volatile(
            "{\n\t"
            ".reg .pred P;\n\t"
            "WAIT_%=:\n\t"
            "mbarrier.try_wait.parity.acquire.cta.shared::cta.b64 P, [%0], 0, 0x989680;\n\t"
            "@P bra.uni DONE_%=;\n\t"
            "bra.uni WAIT_%=;\n\t"
            "DONE_%=:\n\t"
            "}"
            :: "r"(mbar) : "memory");
    }
    __syncthreads();   // publishes TMA data + wsm to all threads

    // ---- compute: acc[ii][m] (f32x2 even-c/odd-c halves), m = cout-4l ----
    ull acc[4][4];
    #pragma unroll
    for (int ii = 0; ii < 4; ii++)
        #pragma unroll
        for (int m = 0; m < 4; m++) acc[ii][m] = 0ull;

    const longlong2* wsm2 = (const longlong2*)wsm;
    // per-thread row base pointers (one IMAD each, then constant offsets)
    const char* xr0 = smem + XSM_OFF + (size_t)g * ROWB;

    #pragma unroll
    for (int jj = 0; jj < 8; jj++) {
        const longlong2 wa0 = wsm2[(2 * jj) * 8 + 2 * l];
        const longlong2 wa1 = wsm2[(2 * jj) * 8 + 2 * l + 1];
        const longlong2 wb0 = wsm2[(2 * jj + 1) * 8 + 2 * l];
        const longlong2 wb1 = wsm2[(2 * jj + 1) * 8 + 2 * l + 1];
        #pragma unroll
        for (int ii = 0; ii < 4; ii++) {
            // bank16 = (r + jj) mod 8: 8 consecutive rows/warp -> 8 banks
            longlong2 xv = *(const longlong2*)(xr0 + ii * (64 * ROWB) + jj * 16);
            const ull xlo = (ull)xv.x;   // channels 4jj, 4jj+1
            const ull xhi = (ull)xv.y;   // channels 4jj+2, 4jj+3
            FMA2(acc[ii][0], xlo, (ull)wa0.x);
            FMA2(acc[ii][1], xlo, (ull)wa0.y);
            FMA2(acc[ii][2], xlo, (ull)wa1.x);
            FMA2(acc[ii][3], xlo, (ull)wa1.y);
            FMA2(acc[ii][0], xhi, (ull)wb0.x);
            FMA2(acc[ii][1], xhi, (ull)wb0.y);
            FMA2(acc[ii][2], xhi, (ull)wb1.x);
            FMA2(acc[ii][3], xhi, (ull)wb1.y);
        }
    }

    // ---- scatter direct from regs: each warp red.v4 = 8 pairs / 8 lines ----
    #pragma unroll
    for (int ii = 0; ii < 4; ii++) {
        if (dsts[ii] < 0) continue;
        float l0, h0, l1, h1, l2, h2, l3, h3;
        UNPACK2(l0, h0, acc[ii][0]);
        UNPACK2(l1, h1, acc[ii][1]);
        UNPACK2(l2, h2, acc[ii][2]);
        UNPACK2(l3, h3, acc[ii][3]);
        float* o = out + (size_t)dsts[ii] * COUT + 4 * l;
        asm volatile("red.global.add.v4.f32 [%0], {%1, %2, %3, %4};"
                     :: "l"(o),
                        "f"(l0 + h0), "f"(l1 + h1),
                        "f"(l2 + h2), "f"(l3 + h3) : "memory");
    }
}

extern "C" void kernel_launch(void* const* d_in, const int* in_sizes, int n_in,
                              void* d_out, int out_size)
{
    const float* x       = (const float*)d_in[0];
    const float* weight  = (const float*)d_in[1];
    const int*   src_idx = (const int*)d_in[2];
    const int*   dst_idx = (const int*)d_in[3];
    float*       out     = (float*)d_out;

    const int K = in_sizes[1] / (CIN * COUT);   // 27
    const int M = in_sizes[2] / K;              // 200000

    cudaMemsetAsync(d_out, 0, (size_t)out_size * sizeof(float), 0);

    cudaFuncSetAttribute(rulebook_gemm_scatter,
                         cudaFuncAttributeMaxDynamicSharedMemorySize, SMEM_BYTES);

    dim3 grid((M + PPB - 1) / PPB, K);
    rulebook_gemm_scatter<<<grid, TPB, SMEM_BYTES>>>(x, weight, src_idx, dst_idx, out, M);
}

// round 15
// speedup vs baseline: 1.0458x; 1.0458x over previous
#include <cuda_runtime.h>
#include <cstdint>

// Sparse transposed conv: gather-GEMM-scatter over rulebook.
// x:[N_SRC,32] f32, weight:[K,32,16] f32, src/dst:[K,M] i32, out:[N_TGT,16] f32.
// v14 = v6 (184us champion) with the kernel body templated on FULL:
//   full tiles (781/782 per k) run with all tail predication removed;
//   only the last partial tile pays the guards. Core unchanged:
//   cp.async staged gather (8 lanes x 16B, xor-swizzled), 4-lane-per-pair
//   ownership, f32x2 FMA, register-direct red.global.add.v4.f32 scatter.

#define CIN   32
#define COUT  16
#define TPB   256
#define PPB   256                 // pairs per block (4 per 4-lane group)
#define NITER ((PPB * 8) / TPB)   // 8 cp.async (16B) per thread

typedef unsigned long long ull;
typedef unsigned int       u32;

#define FMA2(acc, a, b) \
    asm("fma.rn.f32x2 %0, %1, %2, %0;" : "+l"(acc) : "l"(a), "l"(b))

#define UNPACK2(lo, hi, v) \
    asm("mov.b64 {%0, %1}, %2;" : "=f"(lo), "=f"(hi) : "l"(v))

// dynamic smem: [0,2048) wsm (f32x2-interleaved), [2048,+32K) xsm staging
#define XSM_OFF 2048
#define SMEM_BYTES (XSM_OFF + PPB * 8 * 16)   // 34816

template <bool FULL>
__device__ __forceinline__
void tile_body(const float* __restrict__ x,
               const float* __restrict__ w,
               const int*   __restrict__ src_idx,
               const int*   __restrict__ dst_idx,
               float*       __restrict__ out,
               char* smem, u32 xsm_base,
               long long kb, int npair, int k)
{
    float*  wsm = (float*)smem;
    float4* xsm = (float4*)(smem + XSM_OFF);

    // ---- stage gathered rows via cp.async (8 lanes x 16B per row) ----
    // swizzle: slot j -> j ^ ((r>>2)&7): warp's 8 groups hit 8 banks later
    #pragma unroll
    for (int i = 0; i < NITER; i++) {
        int idx = i * TPB + threadIdx.x;
        int r = idx >> 3, j = idx & 7;
        int rc = FULL ? r : ((r < npair) ? r : 0);
        int s = __ldg(src_idx + kb + rc);
        const float4* src = reinterpret_cast<const float4*>(x) + (size_t)s * 8 + j;
        u32 dst = xsm_base + (u32)(r * 8 + (j ^ ((r >> 2) & 7))) * 16;
        asm volatile("cp.async.cg.shared.global [%0], [%1], 16;"
                     :: "r"(dst), "l"(src));
    }
    asm volatile("cp.async.commit_group;");

    // ---- weight[k] -> smem, interleaved: word = cp*32 + j*2 + (c&1) ----
    const float* wk = w + (size_t)k * (CIN * COUT);
    #pragma unroll
    for (int i = 0; i < (CIN * COUT) / TPB; i++) {
        int t = i * TPB + threadIdx.x;
        int c = t >> 4, j = t & 15;
        wsm[(c >> 1) * 32 + j * 2 + (c & 1)] = __ldg(wk + t);
    }

    // group/lane: group g owns pairs g*4..g*4+3; lane l owns couts 4l..4l+3
    const int g = threadIdx.x >> 2;
    const int l = threadIdx.x & 3;

    // prefetch scatter indices while staging drains
    int dsts[4];
    #pragma unroll
    for (int ii = 0; ii < 4; ii++) {
        int r = g * 4 + ii;
        dsts[ii] = (FULL || r < npair) ? __ldg(dst_idx + kb + r) : -1;
    }

    asm volatile("cp.async.wait_group 0;");
    __syncthreads();

    // ---- compute: acc[ii][m] (f32x2: even-c/odd-c halves), m = cout-4l ----
    ull acc[4][4];
    #pragma unroll
    for (int ii = 0; ii < 4; ii++)
        #pragma unroll
        for (int m = 0; m < 4; m++) acc[ii][m] = 0ull;

    const longlong2* wsm2 = (const longlong2*)wsm;
    const int sw = g & 7;

    #pragma unroll
    for (int jj = 0; jj < 8; jj++) {
        // w for cp=2jj,2jj+1 and couts 4l..4l+3 (4-lane spread, 8-way bcast)
        const longlong2 wa0 = wsm2[(2 * jj) * 8 + 2 * l];
        const longlong2 wa1 = wsm2[(2 * jj) * 8 + 2 * l + 1];
        const longlong2 wb0 = wsm2[(2 * jj + 1) * 8 + 2 * l];
        const longlong2 wb1 = wsm2[(2 * jj + 1) * 8 + 2 * l + 1];
        #pragma unroll
        for (int ii = 0; ii < 4; ii++) {
            const int r = g * 4 + ii;
            longlong2 xv = *(const longlong2*)&xsm[r * 8 + (jj ^ sw)];
            const ull xlo = (ull)xv.x;      // channels 4jj, 4jj+1 (cp 2jj)
            const ull xhi = (ull)xv.y;      // channels 4jj+2, 4jj+3 (cp 2jj+1)
            FMA2(acc[ii][0], xlo, (ull)wa0.x);
            FMA2(acc[ii][1], xlo, (ull)wa0.y);
            FMA2(acc[ii][2], xlo, (ull)wa1.x);
            FMA2(acc[ii][3], xlo, (ull)wa1.y);
            FMA2(acc[ii][0], xhi, (ull)wb0.x);
            FMA2(acc[ii][1], xhi, (ull)wb0.y);
            FMA2(acc[ii][2], xhi, (ull)wb1.x);
            FMA2(acc[ii][3], xhi, (ull)wb1.y);
        }
    }

    // ---- scatter direct from regs: each warp red.v4 = 8 pairs / 8 lines ----
    #pragma unroll
    for (int ii = 0; ii < 4; ii++) {
        if (!FULL && dsts[ii] < 0) continue;
        float l0, h0, l1, h1, l2, h2, l3, h3;
        UNPACK2(l0, h0, acc[ii][0]);
        UNPACK2(l1, h1, acc[ii][1]);
        UNPACK2(l2, h2, acc[ii][2]);
        UNPACK2(l3, h3, acc[ii][3]);
        float* o = out + (size_t)dsts[ii] * COUT + 4 * l;
        asm volatile("red.global.add.v4.f32 [%0], {%1, %2, %3, %4};"
                     :: "l"(o),
                        "f"(l0 + h0), "f"(l1 + h1),
                        "f"(l2 + h2), "f"(l3 + h3) : "memory");
    }
}

__global__ __launch_bounds__(TPB, 4)
void rulebook_gemm_scatter(const float* __restrict__ x,
                           const float* __restrict__ w,
                           const int*   __restrict__ src_idx,
                           const int*   __restrict__ dst_idx,
                           float*       __restrict__ out,
                           int M)
{
    extern __shared__ char smem[];

    const int k  = blockIdx.y;
    const int pb = blockIdx.x * PPB;
    const int npair = min(PPB, M - pb);
    const long long kb = (long long)k * M + pb;

    u32 xsm_base;
    asm("{ .reg .u64 t; cvta.to.shared.u64 t, %1; cvt.u32.u64 %0, t; }"
        : "=r"(xsm_base) : "l"(smem + XSM_OFF));

    if (npair == PPB) {
        tile_body<true >(x, w, src_idx, dst_idx, out, smem, xsm_base, kb, npair, k);
    } else {
        tile_body<false>(x, w, src_idx, dst_idx, out, smem, xsm_base, kb, npair, k);
    }
}

extern "C" void kernel_launch(void* const* d_in, const int* in_sizes, int n_in,
                              void* d_out, int out_size)
{
    const float* x       = (const float*)d_in[0];
    const float* weight  = (const float*)d_in[1];
    const int*   src_idx = (const int*)d_in[2];
    const int*   dst_idx = (const int*)d_in[3];
    float*       out     = (float*)d_out;

    const int K = in_sizes[1] / (CIN * COUT);   // 27
    const int M = in_sizes[2] / K;              // 200000

    cudaMemsetAsync(d_out, 0, (size_t)out_size * sizeof(float), 0);

    cudaFuncSetAttribute(rulebook_gemm_scatter,
                         cudaFuncAttributeMaxDynamicSharedMemorySize, SMEM_BYTES);

    dim3 grid((M + PPB - 1) / PPB, K);
    rulebook_gemm_scatter<<<grid, TPB, SMEM_BYTES>>>(x, weight, src_idx, dst_idx, out, M);
}